// round 1
// baseline (speedup 1.0000x reference)
#include <cuda_runtime.h>
#include <stdint.h>

// Channel mask scratch (allocation-free: __device__ global).
__device__ int g_mask[512];

static const int C_CH = 512;
static const int HW = 28 * 28;            // 784 floats per plane
static const int HW4 = HW / 4;            // 196 float4 per plane

// Build the per-channel mask. Single block, 512 threads.
// Self-detects whether indices are int64 or int32:
// values are in [0, 512), so if stored as little-endian int64 every odd
// 32-bit word of the buffer is 0. We test the first 256 int32 words
// (1024 bytes — within bounds for either dtype: int32 buffer is exactly
// 1024 B, int64 buffer is 2048 B).
__global__ void build_mask_kernel(const int* __restrict__ idx32, int n_idx) {
    __shared__ int is64;
    int t = threadIdx.x;
    if (t < C_CH) g_mask[t] = 0;
    if (t == 0) {
        int odd_all_zero = 1;
        for (int i = 1; i < 256; i += 2) {
            if (idx32[i] != 0) { odd_all_zero = 0; break; }
        }
        is64 = odd_all_zero;
    }
    __syncthreads();
    if (t < n_idx) {
        int c = is64 ? idx32[2 * t] : idx32[t];
        if (c >= 0 && c < C_CH) g_mask[c] = 1;   // benign write race (all write 1)
    }
}

// Streaming select: one 16B read from the chosen tensor + one 16B write.
__global__ void replace_kernel(const float4* __restrict__ out_in,
                               const float4* __restrict__ feat,
                               float4* __restrict__ dst,
                               int n4) {
    int i = blockIdx.x * blockDim.x + threadIdx.x;
    if (i >= n4) return;
    int plane = i / HW4;                  // constant division -> mul-hi
    int c = plane & (C_CH - 1);
    const float4* __restrict__ src = g_mask[c] ? feat : out_in;
    dst[i] = src[i];
}

extern "C" void kernel_launch(void* const* d_in, const int* in_sizes, int n_in,
                              void* d_out, int out_size) {
    const float4* out_in = (const float4*)d_in[0];
    const float4* feat   = (const float4*)d_in[1];
    const int*    idx32  = (const int*)d_in[2];   // viewed as int32 words; dtype detected in-kernel
    float4*       dst    = (float4*)d_out;

    int n_idx = in_sizes[2];                       // 256
    int total = in_sizes[0];                       // 32*512*28*28 = 12,845,056
    int n4 = total / 4;                            // 3,211,264

    build_mask_kernel<<<1, 512>>>(idx32, n_idx);

    int threads = 256;
    int blocks = (n4 + threads - 1) / threads;     // 12544
    replace_kernel<<<blocks, threads>>>(out_in, feat, dst, n4);
}

// round 2
// speedup vs baseline: 1.1951x; 1.1951x over previous
#include <cuda_runtime.h>
#include <stdint.h>

static const int C_CH = 512;
static const int HW4 = 196;               // 28*28/4 float4 per plane

// Fused: per-block channel bitmask in smem + 4-way unrolled streaming select.
__global__ void __launch_bounds__(256) fused_replace_kernel(
    const float4* __restrict__ out_in,
    const float4* __restrict__ feat,
    float4* __restrict__ dst,
    const int* __restrict__ idx32,        // raw words of the index buffer
    int n_idx, int n4)
{
    __shared__ unsigned mask[16];          // 512-bit channel mask
    __shared__ int is64;

    int t = threadIdx.x;
    if (t < 16) mask[t] = 0u;
    if (t == 0) is64 = 1;
    __syncthreads();

    // dtype self-detect: values < 512, so little-endian int64 => odd words all 0.
    // 64 odd-word probes (within bounds for int32 too: word 129 < 256).
    if (t < 64) {
        if (idx32[2 * t + 1] != 0) is64 = 0;   // benign race, all write 0
    }
    __syncthreads();
    int i64 = is64;

    if (t < n_idx) {
        int c = i64 ? idx32[2 * t] : idx32[t];
        c &= (C_CH - 1);
        atomicOr(&mask[c >> 5], 1u << (c & 31));
    }
    __syncthreads();

    // 4 independent float4 copies per thread, coalesced, loads front-batched.
    int base   = blockIdx.x * blockDim.x + t;
    int stride = gridDim.x * blockDim.x;

    int i0 = base;
    int i1 = base + stride;
    int i2 = base + 2 * stride;
    int i3 = base + 3 * stride;

    const float4* s0; const float4* s1; const float4* s2; const float4* s3;
    {
        int c0 = (i0 / HW4) & (C_CH - 1);
        int c1 = (i1 / HW4) & (C_CH - 1);
        int c2 = (i2 / HW4) & (C_CH - 1);
        int c3 = (i3 / HW4) & (C_CH - 1);
        s0 = (mask[c0 >> 5] >> (c0 & 31)) & 1u ? feat : out_in;
        s1 = (mask[c1 >> 5] >> (c1 & 31)) & 1u ? feat : out_in;
        s2 = (mask[c2 >> 5] >> (c2 & 31)) & 1u ? feat : out_in;
        s3 = (mask[c3 >> 5] >> (c3 & 31)) & 1u ? feat : out_in;
    }

    float4 v0, v1, v2, v3;
    bool p0 = i0 < n4, p1 = i1 < n4, p2 = i2 < n4, p3 = i3 < n4;
    if (p0) v0 = s0[i0];
    if (p1) v1 = s1[i1];
    if (p2) v2 = s2[i2];
    if (p3) v3 = s3[i3];
    if (p0) dst[i0] = v0;
    if (p1) dst[i1] = v1;
    if (p2) dst[i2] = v2;
    if (p3) dst[i3] = v3;
}

extern "C" void kernel_launch(void* const* d_in, const int* in_sizes, int n_in,
                              void* d_out, int out_size) {
    const float4* out_in = (const float4*)d_in[0];
    const float4* feat   = (const float4*)d_in[1];
    const int*    idx32  = (const int*)d_in[2];
    float4*       dst    = (float4*)d_out;

    int n_idx = in_sizes[2];                // 256
    int total = in_sizes[0];                // 12,845,056
    int n4 = total / 4;                     // 3,211,264

    const int threads = 256;
    const int per_thread = 4;
    int blocks = (n4 + threads * per_thread - 1) / (threads * per_thread);  // 3136

    fused_replace_kernel<<<blocks, threads>>>(out_in, feat, dst, idx32, n_idx, n4);
}

// round 3
// speedup vs baseline: 1.2186x; 1.0197x over previous
#include <cuda_runtime.h>
#include <stdint.h>

static const int C_CH = 512;
static const int HW4 = 196;               // 28*28/4 float4 per plane
static const int PER_THREAD = 8;

__global__ void __launch_bounds__(256) fused_replace_kernel(
    const float4* __restrict__ out_in,
    const float4* __restrict__ feat,
    float4* __restrict__ dst,
    const int* __restrict__ idx32,
    int n_idx, int n4)
{
    __shared__ unsigned mask[16];          // 512-bit channel mask
    __shared__ int is64;

    int t = threadIdx.x;
    if (t < 16) mask[t] = 0u;
    if (t == 0) is64 = 1;
    __syncthreads();

    // dtype self-detect: values < 512 => little-endian int64 has all odd words 0.
    if (t < 64) {
        if (idx32[2 * t + 1] != 0) is64 = 0;   // benign race
    }
    __syncthreads();
    int i64 = is64;

    if (t < n_idx) {
        int c = i64 ? idx32[2 * t] : idx32[t];
        c &= (C_CH - 1);
        atomicOr(&mask[c >> 5], 1u << (c & 31));
    }
    __syncthreads();

    int base   = blockIdx.x * blockDim.x + t;
    int stride = gridDim.x * blockDim.x;

    int idx[PER_THREAD];
    const float4* src[PER_THREAD];
    #pragma unroll
    for (int k = 0; k < PER_THREAD; k++) {
        idx[k] = base + k * stride;
        int c = (idx[k] / HW4) & (C_CH - 1);
        src[k] = (mask[c >> 5] >> (c & 31)) & 1u ? feat : out_in;
    }

    float4 v[PER_THREAD];
    #pragma unroll
    for (int k = 0; k < PER_THREAD; k++)
        if (idx[k] < n4) v[k] = __ldcs(&src[k][idx[k]]);   // evict-first streaming load
    #pragma unroll
    for (int k = 0; k < PER_THREAD; k++)
        if (idx[k] < n4) __stcs(&dst[idx[k]], v[k]);       // evict-first streaming store
}

extern "C" void kernel_launch(void* const* d_in, const int* in_sizes, int n_in,
                              void* d_out, int out_size) {
    const float4* out_in = (const float4*)d_in[0];
    const float4* feat   = (const float4*)d_in[1];
    const int*    idx32  = (const int*)d_in[2];
    float4*       dst    = (float4*)d_out;

    int n_idx = in_sizes[2];                 // 256
    int total = in_sizes[0];                 // 12,845,056
    int n4 = total / 4;                      // 3,211,264

    const int threads = 256;
    int blocks = (n4 + threads * PER_THREAD - 1) / (threads * PER_THREAD);  // 1568

    fused_replace_kernel<<<blocks, threads>>>(out_in, feat, dst, idx32, n_idx, n4);
}